// round 15
// baseline (speedup 1.0000x reference)
#include <cuda_runtime.h>
#include <cuda_fp16.h>
#include <cstdint>

#define NN 8192
#define DD 1024

// Scratch buffers.
__device__ __align__(256) uint32_t g_Sp[(size_t)NN * NN / 2];    // P=exp(S), A-permuted fp16 (128 MB)
__device__ __align__(256) uint32_t g_Ap[(size_t)NN * DD / 2];    // Q*scale, A-permuted fp16
__device__ __align__(256) uint32_t g_Bk[(size_t)NN * DD / 2];    // K, B-permuted fp16
__device__ __align__(256) uint32_t g_Bv[(size_t)DD * NN / 2];    // V^T, B-permuted fp16
__device__ __align__(256) float    g_part[(size_t)(NN / 128) * NN];  // [bncta][row] partials
__device__ float g_rowinv[NN];

// ---------------------------------------------------------------------------
// Helpers
// ---------------------------------------------------------------------------
__device__ __forceinline__ uint32_t smem_u32(const void* p) {
    uint32_t a;
    asm("{ .reg .u64 t; cvta.to.shared.u64 t, %1; cvt.u32.u64 %0, t; }" : "=r"(a) : "l"(p));
    return a;
}

__device__ __forceinline__ void cp_async16(uint32_t saddr, const void* gaddr) {
    asm volatile("cp.async.cg.shared.global [%0], [%1], 16;" :: "r"(saddr), "l"(gaddr) : "memory");
}

__device__ __forceinline__ void mma_f16(float* c, const uint32_t* a, const uint32_t* b) {
    asm volatile(
        "mma.sync.aligned.m16n8k16.row.col.f32.f16.f16.f32 "
        "{%0,%1,%2,%3}, {%4,%5,%6,%7}, {%8,%9}, {%0,%1,%2,%3};"
        : "+f"(c[0]), "+f"(c[1]), "+f"(c[2]), "+f"(c[3])
        : "r"(a[0]), "r"(a[1]), "r"(a[2]), "r"(a[3]), "r"(b[0]), "r"(b[1]));
}

__device__ __forceinline__ uint32_t pack_h2(float lo, float hi) {
    __half2 h = __floats2half2_rn(lo, hi);
    return *(uint32_t*)&h;
}

// Fast exp(x) via 2^t poly + exponent bit-trick. FMA/ALU pipe only.
__device__ __forceinline__ float fexp(float x) {
    x = fmaxf(x, -80.0f);
    const float L2E = 1.4426950408889634f;
    float z = fmaf(x, L2E, 12582912.0f);
    float r = z - 12582912.0f;
    float f = fmaf(x, L2E, -r);
    float p =              1.3333558e-3f;
    p = fmaf(p, f,         9.6181291e-3f);
    p = fmaf(p, f,         5.5504109e-2f);
    p = fmaf(p, f,         2.4022651e-1f);
    p = fmaf(p, f,         6.9314718e-1f);
    p = fmaf(p, f,         1.0f);
    int e = (__float_as_int(z) + (127 - 0x4B400000)) << 23;
    return p * __int_as_float(e);
}

// ---------------------------------------------------------------------------
// Layouts (fp16 m16n8k16 fragments, K-tile = 16):
// A: [M/16][K/16][128 u32], inner = (m&15)*8 + ((k>>1)&3)*2 + ((k>>3)&1), half=k&1
// B: [N/8 ][K/16][ 64 u32], inner = ((n&7)*4 + ((k>>1)&3))*2 + ((k>>3)&1), half=k&1
// ---------------------------------------------------------------------------

__global__ __launch_bounds__(256) void prep_q(const float* __restrict__ Q) {
    const size_t o = (size_t)blockIdx.x * 256 + threadIdx.x;
    const int tile = (int)(o >> 7), w = (int)(o & 127);
    const int mt = tile >> 6, kt = tile & 63;
    const int m = mt * 16 + (w >> 3);
    const int k = kt * 16 + (w & 1) * 8 + ((w >> 1) & 3) * 2;
    const float* src = Q + (size_t)m * DD + k;
    g_Ap[o] = pack_h2(src[0] * 0.03125f, src[1] * 0.03125f);
}
__global__ __launch_bounds__(256) void prep_k(const float* __restrict__ K) {
    const size_t o = (size_t)blockIdx.x * 256 + threadIdx.x;
    const int tile = (int)(o >> 6), w = (int)(o & 63);
    const int nt = tile >> 6, kt = tile & 63;
    const int t = w >> 1, reg = w & 1;
    const int n = nt * 8 + (t >> 2);
    const int k = kt * 16 + reg * 8 + (t & 3) * 2;
    const float* src = K + (size_t)n * DD + k;
    g_Bk[o] = pack_h2(src[0], src[1]);
}
__global__ __launch_bounds__(256) void prep_v(const float* __restrict__ V) {
    const size_t o = (size_t)blockIdx.x * 256 + threadIdx.x;
    const int tile = (int)(o >> 6), w = (int)(o & 63);
    const int nt = tile >> 9, kt = tile & 511;
    const int t = w >> 1, reg = w & 1;
    const int d = nt * 8 + (t >> 2);
    const int s = kt * 16 + reg * 8 + (t & 3) * 2;
    g_Bv[o] = pack_h2(V[(size_t)s * DD + d], V[(size_t)(s + 1) * DD + d]);
}

// ---------------------------------------------------------------------------
// Unified NT fp16 GEMM: CTA 128x128, BK=64 (4 k-subtiles/stage), 8 warps
// (2M x 4N, warp tile 64x32), 3-stage cp.async (32 KB/stage, 96 KB dynamic),
// 1 sync per 4 k-subtiles, bF prefetched one subtile ahead, 2 CTAs/SM.
// mode 0 (QK): epilogue = exp() -> fp16 permuted g_Sp + row-sum partials
// mode 1 (PV): epilogue = acc * rowinv[m] -> fp32 C
// ---------------------------------------------------------------------------
struct GemmParams {
    const uint32_t* Ap;
    const uint32_t* Bp;
    float* C;
    const float* rowinv;
    int ldc;
    int KT;      // K / 16  (multiple of 4)
    int mode;
};

#define STAGES 3
#define STG_U32 8192            // 4 x [A 1024 | B 1024]
#define STG_BYTES (STG_U32 * 4) // 32768
#define SMEM_TOTAL (STAGES * STG_BYTES)   // 98304

__global__ __launch_bounds__(256, 2) void gemm_fp16(const GemmParams p) {
    extern __shared__ uint32_t smem[];

    const int tid = threadIdx.x;
    const int wid = tid >> 5, lane = tid & 31;
    const int wm = wid & 1, wn = wid >> 1;
    const int bmt = blockIdx.y * 8;           // m/16 subtile base
    const int bnt = blockIdx.x * 16;          // n/8 subtile base
    const int IT = p.KT >> 2;                 // iterations (4 kt each)

    const uint32_t* Ag = p.Ap + ((size_t)(bmt + (tid >> 5)) * p.KT) * 128 + (tid & 31) * 4;
    const uint32_t* Bg = p.Bp + ((size_t)(bnt + (tid >> 4)) * p.KT) * 64 + (tid & 15) * 4;
    const uint32_t sbase = smem_u32(smem);
    const uint32_t sA = sbase + tid * 16;            // + stage*STG_BYTES + j*8192
    const uint32_t sB = sbase + 4096 + tid * 16;

    float acc[4][4][4];
#pragma unroll
    for (int i = 0; i < 4; i++)
#pragma unroll
        for (int j = 0; j < 4; j++)
#pragma unroll
            for (int r = 0; r < 4; r++) acc[i][j][r] = 0.0f;

    // prologue: stages 0..1 (4 subtiles each)
#pragma unroll
    for (int s = 0; s < STAGES - 1; s++) {
#pragma unroll
        for (int j = 0; j < 4; j++) {
            cp_async16(sA + s * STG_BYTES + j * 8192, Ag + (size_t)(4 * s + j) * 128);
            cp_async16(sB + s * STG_BYTES + j * 8192, Bg + (size_t)(4 * s + j) * 64);
        }
        asm volatile("cp.async.commit_group;" ::: "memory");
    }

    int stg = 0;        // stage being consumed
    int wstg = 2;       // stage being refilled

    for (int it = 0; it < IT; it++) {
        asm volatile("cp.async.wait_group 1;" ::: "memory");
        __syncthreads();

        const int ns = it + STAGES - 1;
        if (ns < IT) {
#pragma unroll
            for (int j = 0; j < 4; j++) {
                cp_async16(sA + wstg * STG_BYTES + j * 8192, Ag + (size_t)(4 * ns + j) * 128);
                cp_async16(sB + wstg * STG_BYTES + j * 8192, Bg + (size_t)(4 * ns + j) * 64);
            }
        }
        asm volatile("cp.async.commit_group;" ::: "memory");

        const uint32_t* stgA = smem + stg * STG_U32;

        // bF double buffer: prefetch one subtile ahead
        uint2 bF[2][4];
#pragma unroll
        for (int nt = 0; nt < 4; nt++)
            bF[0][nt] = *(const uint2*)(stgA + 1024 + (wn * 4 + nt) * 64 + lane * 2);

#pragma unroll
        for (int j = 0; j < 4; j++) {
            const uint32_t* bufA = stgA + j * 2048;
            if (j < 3) {
                const uint32_t* nb = stgA + (j + 1) * 2048 + 1024;
#pragma unroll
                for (int nt = 0; nt < 4; nt++)
                    bF[(j + 1) & 1][nt] = *(const uint2*)(nb + (wn * 4 + nt) * 64 + lane * 2);
            }
#pragma unroll
            for (int mt = 0; mt < 4; mt++) {
                const uint32_t* ab = bufA + (wm * 4 + mt) * 128 + (lane >> 2) * 8 + (lane & 3) * 2;
                const uint2 lo = *(const uint2*)ab;
                const uint2 hi = *(const uint2*)(ab + 64);
                uint32_t a[4] = {lo.x, hi.x, lo.y, hi.y};
#pragma unroll
                for (int nt = 0; nt < 4; nt++) {
                    uint32_t b[2] = {bF[j & 1][nt].x, bF[j & 1][nt].y};
                    mma_f16(acc[mt][nt], a, b);
                }
            }
        }

        stg = (stg + 1 == STAGES) ? 0 : stg + 1;
        wstg = (wstg + 1 == STAGES) ? 0 : wstg + 1;
    }

    const int bm = blockIdx.y * 128, bn = blockIdx.x * 128;

    if (p.mode == 0) {
        // ---- QK epilogue: exp -> fp16 permuted g_Sp (STG.64) + row sums ----
        __syncthreads();
        float* spart = (float*)smem;           // [128][4]

#pragma unroll
        for (int mt = 0; mt < 4; mt++) {
            const int lr = wm * 64 + mt * 16 + (lane >> 2);
            float s0 = 0.0f, s1 = 0.0f;
            const int innerA0 = (lane >> 2) * 8 + (lane & 3) * 2;
#pragma unroll
            for (int pr = 0; pr < 2; pr++) {            // nt pairs {0,1},{2,3}
                const int n0 = pr * 2, n1 = pr * 2 + 1;
                const float a0 = fexp(acc[mt][n0][0]), a1 = fexp(acc[mt][n0][1]);
                const float a2 = fexp(acc[mt][n0][2]), a3 = fexp(acc[mt][n0][3]);
                const float b0 = fexp(acc[mt][n1][0]), b1 = fexp(acc[mt][n1][1]);
                const float b2 = fexp(acc[mt][n1][2]), b3 = fexp(acc[mt][n1][3]);
                s0 += (a0 + a1) + (b0 + b1);
                s1 += (a2 + a3) + (b2 + b3);
                const int kt2 = (bn >> 4) + wn * 2 + pr;
                const size_t base = ((size_t)((bm + lr) >> 4) * (NN / 16) + kt2) * 128;
                uint2 w0 = make_uint2(pack_h2(a0, a1), pack_h2(b0, b1));   // row r
                uint2 w1 = make_uint2(pack_h2(a2, a3), pack_h2(b2, b3));   // row r+8
                *(uint2*)(g_Sp + base + innerA0)      = w0;
                *(uint2*)(g_Sp + base + innerA0 + 64) = w1;
            }
            s0 += __shfl_xor_sync(0xFFFFFFFFu, s0, 1);
            s0 += __shfl_xor_sync(0xFFFFFFFFu, s0, 2);
            s1 += __shfl_xor_sync(0xFFFFFFFFu, s1, 1);
            s1 += __shfl_xor_sync(0xFFFFFFFFu, s1, 2);
            if ((lane & 3) == 0) {
                spart[lr * 4 + wn]       = s0;
                spart[(lr + 8) * 4 + wn] = s1;
            }
        }
        __syncthreads();
        if (tid < 128) {
            const float t = spart[tid * 4] + spart[tid * 4 + 1]
                          + spart[tid * 4 + 2] + spart[tid * 4 + 3];
            g_part[(size_t)blockIdx.x * NN + bm + tid] = t;
        }
    } else {
        // ---- PV epilogue: divide by rowsum, write fp32 output ----
#pragma unroll
        for (int mt = 0; mt < 4; mt++) {
            const int row = bm + wm * 64 + mt * 16 + (lane >> 2);
            const float f0 = p.rowinv[row];
            const float f1 = p.rowinv[row + 8];
#pragma unroll
            for (int nt = 0; nt < 4; nt++) {
                const int col = bn + wn * 32 + nt * 8 + (lane & 3) * 2;
                float2 o0 = make_float2(acc[mt][nt][0] * f0, acc[mt][nt][1] * f0);
                float2 o1 = make_float2(acc[mt][nt][2] * f1, acc[mt][nt][3] * f1);
                *(float2*)(p.C + (size_t)row * p.ldc + col)       = o0;
                *(float2*)(p.C + (size_t)(row + 8) * p.ldc + col) = o1;
            }
        }
    }
}

// ---------------------------------------------------------------------------
// Row-sum reduction: g_rowinv[r] = 1 / sum_b g_part[b][r]   (fixed order)
// ---------------------------------------------------------------------------
__global__ __launch_bounds__(256) void reduce_rowsum() {
    const int r = blockIdx.x * 256 + threadIdx.x;
    float s = 0.0f;
#pragma unroll 8
    for (int b = 0; b < NN / 128; b++) s += g_part[(size_t)b * NN + r];
    g_rowinv[r] = 1.0f / s;
}

// ---------------------------------------------------------------------------
// Host
// ---------------------------------------------------------------------------
extern "C" void kernel_launch(void* const* d_in, const int* in_sizes, int n_in,
                              void* d_out, int out_size) {
    const float* q = (const float*)d_in[0];
    const float* k = (const float*)d_in[1];
    const float* v = (const float*)d_in[2];
    float* out = (float*)d_out;

    void *pSp = nullptr, *pAp = nullptr, *pBk = nullptr, *pBv = nullptr, *pRi = nullptr;
    cudaGetSymbolAddress(&pSp, g_Sp);
    cudaGetSymbolAddress(&pAp, g_Ap);
    cudaGetSymbolAddress(&pBk, g_Bk);
    cudaGetSymbolAddress(&pBv, g_Bv);
    cudaGetSymbolAddress(&pRi, g_rowinv);

    cudaFuncSetAttribute(gemm_fp16, cudaFuncAttributeMaxDynamicSharedMemorySize, SMEM_TOTAL);

    const int half_words = (int)(((size_t)NN * DD) / 2);
    prep_q<<<half_words / 256, 256>>>(q);
    prep_k<<<half_words / 256, 256>>>(k);
    prep_v<<<half_words / 256, 256>>>(v);

    GemmParams g1;
    g1.Ap = (const uint32_t*)pAp; g1.Bp = (const uint32_t*)pBk;
    g1.C = nullptr; g1.rowinv = nullptr;
    g1.ldc = NN; g1.KT = DD / 16; g1.mode = 0;
    gemm_fp16<<<dim3(NN / 128, NN / 128), 256, SMEM_TOTAL>>>(g1);

    reduce_rowsum<<<NN / 256, 256>>>();

    GemmParams g2;
    g2.Ap = (const uint32_t*)pSp; g2.Bp = (const uint32_t*)pBv;
    g2.C = out; g2.rowinv = (const float*)pRi;
    g2.ldc = DD; g2.KT = NN / 16; g2.mode = 1;
    gemm_fp16<<<dim3(DD / 128, NN / 128), 256, SMEM_TOTAL>>>(g2);
}

// round 17
// speedup vs baseline: 1.0055x; 1.0055x over previous
#include <cuda_runtime.h>
#include <cuda_fp16.h>
#include <cstdint>

#define NN 8192
#define DD 1024

// Scratch buffers.
__device__ __align__(256) uint32_t g_Sp[(size_t)NN * NN / 2];    // P=exp(S), A-permuted fp16 (128 MB)
__device__ __align__(256) uint32_t g_Ap[(size_t)NN * DD / 2];    // Q*scale, A-permuted fp16
__device__ __align__(256) uint32_t g_Bk[(size_t)NN * DD / 2];    // K, B-permuted fp16
__device__ __align__(256) uint32_t g_Bv[(size_t)DD * NN / 2];    // V^T, B-permuted fp16
__device__ __align__(256) float    g_part[(size_t)(NN / 128) * NN];  // [bncta][row] partials
__device__ float g_rowinv[NN];

// ---------------------------------------------------------------------------
// Helpers
// ---------------------------------------------------------------------------
__device__ __forceinline__ uint32_t smem_u32(const void* p) {
    uint32_t a;
    asm("{ .reg .u64 t; cvta.to.shared.u64 t, %1; cvt.u32.u64 %0, t; }" : "=r"(a) : "l"(p));
    return a;
}

__device__ __forceinline__ void cp_async16(uint32_t saddr, const void* gaddr) {
    asm volatile("cp.async.cg.shared.global [%0], [%1], 16;" :: "r"(saddr), "l"(gaddr) : "memory");
}

__device__ __forceinline__ void mma_f16(float* c, const uint32_t* a, const uint32_t* b) {
    asm volatile(
        "mma.sync.aligned.m16n8k16.row.col.f32.f16.f16.f32 "
        "{%0,%1,%2,%3}, {%4,%5,%6,%7}, {%8,%9}, {%0,%1,%2,%3};"
        : "+f"(c[0]), "+f"(c[1]), "+f"(c[2]), "+f"(c[3])
        : "r"(a[0]), "r"(a[1]), "r"(a[2]), "r"(a[3]), "r"(b[0]), "r"(b[1]));
}

__device__ __forceinline__ uint32_t pack_h2(float lo, float hi) {
    __half2 h = __floats2half2_rn(lo, hi);
    return *(uint32_t*)&h;
}

// Fast exp(x) via 2^t poly + exponent bit-trick. FMA/ALU pipe only.
__device__ __forceinline__ float fexp(float x) {
    x = fmaxf(x, -80.0f);
    const float L2E = 1.4426950408889634f;
    float z = fmaf(x, L2E, 12582912.0f);
    float r = z - 12582912.0f;
    float f = fmaf(x, L2E, -r);
    float p =              1.3333558e-3f;
    p = fmaf(p, f,         9.6181291e-3f);
    p = fmaf(p, f,         5.5504109e-2f);
    p = fmaf(p, f,         2.4022651e-1f);
    p = fmaf(p, f,         6.9314718e-1f);
    p = fmaf(p, f,         1.0f);
    int e = (__float_as_int(z) + (127 - 0x4B400000)) << 23;
    return p * __int_as_float(e);
}

// ---------------------------------------------------------------------------
// Layouts (fp16 m16n8k16 fragments, K-tile = 16):
// A (fragment-direct): [M/16][K/16][128 u32],
//   inner = lane*4 + reg,  lane = (m&7)*4 + ((k>>1)&3),
//   reg = ((m>>3)&1) + 2*((k>>3)&1),  half = k&1
//   -> thread's 4 regs contiguous: ONE LDS.128 / STG.128 per fragment.
// B: [N/8][K/16][64 u32], inner = ((n&7)*4 + ((k>>1)&3))*2 + ((k>>3)&1), half=k&1
// ---------------------------------------------------------------------------

__global__ __launch_bounds__(256) void prep_q(const float* __restrict__ Q) {
    const size_t o = (size_t)blockIdx.x * 256 + threadIdx.x;
    const int tile = (int)(o >> 7), w = (int)(o & 127);
    const int mt = tile >> 6, kt = tile & 63;
    const int lane = w >> 2, reg = w & 3;
    const int m = mt * 16 + (lane >> 2) + ((reg & 1) << 3);
    const int k = kt * 16 + (lane & 3) * 2 + ((reg >> 1) << 3);
    const float* src = Q + (size_t)m * DD + k;
    g_Ap[o] = pack_h2(src[0] * 0.03125f, src[1] * 0.03125f);
}
__global__ __launch_bounds__(256) void prep_k(const float* __restrict__ K) {
    const size_t o = (size_t)blockIdx.x * 256 + threadIdx.x;
    const int tile = (int)(o >> 6), w = (int)(o & 63);
    const int nt = tile >> 6, kt = tile & 63;
    const int t = w >> 1, reg = w & 1;
    const int n = nt * 8 + (t >> 2);
    const int k = kt * 16 + reg * 8 + (t & 3) * 2;
    const float* src = K + (size_t)n * DD + k;
    g_Bk[o] = pack_h2(src[0], src[1]);
}
__global__ __launch_bounds__(256) void prep_v(const float* __restrict__ V) {
    const size_t o = (size_t)blockIdx.x * 256 + threadIdx.x;
    const int tile = (int)(o >> 6), w = (int)(o & 63);
    const int nt = tile >> 9, kt = tile & 511;
    const int t = w >> 1, reg = w & 1;
    const int d = nt * 8 + (t >> 2);
    const int s = kt * 16 + reg * 8 + (t & 3) * 2;
    g_Bv[o] = pack_h2(V[(size_t)s * DD + d], V[(size_t)(s + 1) * DD + d]);
}

// ---------------------------------------------------------------------------
// Unified NT fp16 GEMM: CTA 128x128, BK=32 (2 k-subtiles/stage), 8 warps
// (2M x 4N, warp tile 64x32), 4-stage cp.async (16 KB/stage, 64 KB dynamic),
// 1 sync per 2 k-subtiles, 2 CTAs/SM. A fragments via single LDS.128.
// mode 0 (QK): epilogue = exp() -> fp16 permuted g_Sp (STG.128) + row sums
// mode 1 (PV): epilogue = acc * rowinv[m] -> fp32 C
// ---------------------------------------------------------------------------
struct GemmParams {
    const uint32_t* Ap;
    const uint32_t* Bp;
    float* C;
    const float* rowinv;
    int ldc;
    int KT;      // K / 16  (even)
    int mode;
};

#define STAGES 4
#define STG_U32 4096            // [A0 1024 | B0 1024 | A1 1024 | B1 1024]
#define STG_BYTES (STG_U32 * 4)
#define SMEM_TOTAL (STAGES * STG_BYTES)   // 65536

__global__ __launch_bounds__(256, 2) void gemm_fp16(const GemmParams p) {
    extern __shared__ uint32_t smem[];

    const int tid = threadIdx.x;
    const int wid = tid >> 5, lane = tid & 31;
    const int wm = wid & 1, wn = wid >> 1;
    const int bmt = blockIdx.y * 8;           // m/16 subtile base
    const int bnt = blockIdx.x * 16;          // n/8 subtile base
    const int IT = p.KT >> 1;                 // iterations (2 kt each)

    const uint32_t* Ag = p.Ap + ((size_t)(bmt + (tid >> 5)) * p.KT) * 128 + (tid & 31) * 4;
    const uint32_t* Bg = p.Bp + ((size_t)(bnt + (tid >> 4)) * p.KT) * 64 + (tid & 15) * 4;
    const uint32_t sbase = smem_u32(smem);
    const uint32_t sA = sbase + tid * 16;            // + stage*16384 + j*8192
    const uint32_t sB = sbase + 4096 + tid * 16;

    float acc[4][4][4];
#pragma unroll
    for (int i = 0; i < 4; i++)
#pragma unroll
        for (int j = 0; j < 4; j++)
#pragma unroll
            for (int r = 0; r < 4; r++) acc[i][j][r] = 0.0f;

    // prologue: stages 0..2 (kt pairs)
#pragma unroll
    for (int s = 0; s < STAGES - 1; s++) {
#pragma unroll
        for (int j = 0; j < 2; j++) {
            cp_async16(sA + s * STG_BYTES + j * 8192, Ag + (size_t)(2 * s + j) * 128);
            cp_async16(sB + s * STG_BYTES + j * 8192, Bg + (size_t)(2 * s + j) * 64);
        }
        asm volatile("cp.async.commit_group;" ::: "memory");
    }

    for (int it = 0; it < IT; it++) {
        asm volatile("cp.async.wait_group 2;" ::: "memory");
        __syncthreads();

        const int ns = it + STAGES - 1;
        if (ns < IT) {
            const int st = ns & (STAGES - 1);
#pragma unroll
            for (int j = 0; j < 2; j++) {
                cp_async16(sA + st * STG_BYTES + j * 8192, Ag + (size_t)(2 * ns + j) * 128);
                cp_async16(sB + st * STG_BYTES + j * 8192, Bg + (size_t)(2 * ns + j) * 64);
            }
        }
        asm volatile("cp.async.commit_group;" ::: "memory");

#pragma unroll
        for (int j = 0; j < 2; j++) {
            const uint32_t* bufA = smem + (it & (STAGES - 1)) * STG_U32 + j * 2048;
            const uint32_t* bufB = bufA + 1024;

            uint2 bF[4];
#pragma unroll
            for (int nt = 0; nt < 4; nt++)
                bF[nt] = *(const uint2*)(bufB + (wn * 4 + nt) * 64 + lane * 2);

#pragma unroll
            for (int mt = 0; mt < 4; mt++) {
                const uint4 av = *(const uint4*)(bufA + (wm * 4 + mt) * 128 + lane * 4);
                uint32_t a[4] = {av.x, av.y, av.z, av.w};
#pragma unroll
                for (int nt = 0; nt < 4; nt++) {
                    uint32_t b[2] = {bF[nt].x, bF[nt].y};
                    mma_f16(acc[mt][nt], a, b);
                }
            }
        }
    }

    const int bm = blockIdx.y * 128, bn = blockIdx.x * 128;

    if (p.mode == 0) {
        // ---- QK epilogue: exp -> fp16 fragment-direct g_Sp (STG.128) + sums ----
        __syncthreads();
        float* spart = (float*)smem;           // [128][4]

#pragma unroll
        for (int mt = 0; mt < 4; mt++) {
            const int lr = wm * 64 + mt * 16 + (lane >> 2);
            const int mt16 = (bm >> 4) + wm * 4 + mt;         // (bm+lr)>>4
            float s0 = 0.0f, s1 = 0.0f;
#pragma unroll
            for (int pr = 0; pr < 2; pr++) {            // nt pairs {0,1},{2,3}
                const int n0 = pr * 2, n1 = pr * 2 + 1;
                const float a0 = fexp(acc[mt][n0][0]), a1 = fexp(acc[mt][n0][1]);
                const float a2 = fexp(acc[mt][n0][2]), a3 = fexp(acc[mt][n0][3]);
                const float b0 = fexp(acc[mt][n1][0]), b1 = fexp(acc[mt][n1][1]);
                const float b2 = fexp(acc[mt][n1][2]), b3 = fexp(acc[mt][n1][3]);
                s0 += (a0 + a1) + (b0 + b1);
                s1 += (a2 + a3) + (b2 + b3);
                const int kt2 = (bn >> 4) + wn * 2 + pr;
                const size_t base = ((size_t)mt16 * (NN / 16) + kt2) * 128;
                // fragment-direct: reg0=(r,klo) reg1=(r+8,klo) reg2=(r,khi) reg3=(r+8,khi)
                uint4 w4 = make_uint4(pack_h2(a0, a1), pack_h2(a2, a3),
                                      pack_h2(b0, b1), pack_h2(b2, b3));
                *(uint4*)(g_Sp + base + lane * 4) = w4;
            }
            s0 += __shfl_xor_sync(0xFFFFFFFFu, s0, 1);
            s0 += __shfl_xor_sync(0xFFFFFFFFu, s0, 2);
            s1 += __shfl_xor_sync(0xFFFFFFFFu, s1, 1);
            s1 += __shfl_xor_sync(0xFFFFFFFFu, s1, 2);
            if ((lane & 3) == 0) {
                spart[lr * 4 + wn]       = s0;
                spart[(lr + 8) * 4 + wn] = s1;
            }
        }
        __syncthreads();
        if (tid < 128) {
            const float t = spart[tid * 4] + spart[tid * 4 + 1]
                          + spart[tid * 4 + 2] + spart[tid * 4 + 3];
            g_part[(size_t)blockIdx.x * NN + bm + tid] = t;
        }
    } else {
        // ---- PV epilogue: divide by rowsum, write fp32 output ----
#pragma unroll
        for (int mt = 0; mt < 4; mt++) {
            const int row = bm + wm * 64 + mt * 16 + (lane >> 2);
            const float f0 = p.rowinv[row];
            const float f1 = p.rowinv[row + 8];
#pragma unroll
            for (int nt = 0; nt < 4; nt++) {
                const int col = bn + wn * 32 + nt * 8 + (lane & 3) * 2;
                float2 o0 = make_float2(acc[mt][nt][0] * f0, acc[mt][nt][1] * f0);
                float2 o1 = make_float2(acc[mt][nt][2] * f1, acc[mt][nt][3] * f1);
                *(float2*)(p.C + (size_t)row * p.ldc + col)       = o0;
                *(float2*)(p.C + (size_t)(row + 8) * p.ldc + col) = o1;
            }
        }
    }
}

// ---------------------------------------------------------------------------
// Row-sum reduction: g_rowinv[r] = 1 / sum_b g_part[b][r]   (fixed order)
// ---------------------------------------------------------------------------
__global__ __launch_bounds__(256) void reduce_rowsum() {
    const int r = blockIdx.x * 256 + threadIdx.x;
    float s = 0.0f;
#pragma unroll 8
    for (int b = 0; b < NN / 128; b++) s += g_part[(size_t)b * NN + r];
    g_rowinv[r] = 1.0f / s;
}

// ---------------------------------------------------------------------------
// Host
// ---------------------------------------------------------------------------
extern "C" void kernel_launch(void* const* d_in, const int* in_sizes, int n_in,
                              void* d_out, int out_size) {
    const float* q = (const float*)d_in[0];
    const float* k = (const float*)d_in[1];
    const float* v = (const float*)d_in[2];
    float* out = (float*)d_out;

    void *pSp = nullptr, *pAp = nullptr, *pBk = nullptr, *pBv = nullptr, *pRi = nullptr;
    cudaGetSymbolAddress(&pSp, g_Sp);
    cudaGetSymbolAddress(&pAp, g_Ap);
    cudaGetSymbolAddress(&pBk, g_Bk);
    cudaGetSymbolAddress(&pBv, g_Bv);
    cudaGetSymbolAddress(&pRi, g_rowinv);

    cudaFuncSetAttribute(gemm_fp16, cudaFuncAttributeMaxDynamicSharedMemorySize, SMEM_TOTAL);

    const int half_words = (int)(((size_t)NN * DD) / 2);
    prep_q<<<half_words / 256, 256>>>(q);
    prep_k<<<half_words / 256, 256>>>(k);
    prep_v<<<half_words / 256, 256>>>(v);

    GemmParams g1;
    g1.Ap = (const uint32_t*)pAp; g1.Bp = (const uint32_t*)pBk;
    g1.C = nullptr; g1.rowinv = nullptr;
    g1.ldc = NN; g1.KT = DD / 16; g1.mode = 0;
    gemm_fp16<<<dim3(NN / 128, NN / 128), 256, SMEM_TOTAL>>>(g1);

    reduce_rowsum<<<NN / 256, 256>>>();

    GemmParams g2;
    g2.Ap = (const uint32_t*)pSp; g2.Bp = (const uint32_t*)pBv;
    g2.C = out; g2.rowinv = (const float*)pRi;
    g2.ldc = DD; g2.KT = NN / 16; g2.mode = 1;
    gemm_fp16<<<dim3(DD / 128, NN / 128), 256, SMEM_TOTAL>>>(g2);
}